// round 1
// baseline (speedup 1.0000x reference)
#include <cuda_runtime.h>
#include <math.h>

#define NV    150000
#define NFACE 300000

// ---------------- scratch (device globals; no allocs allowed) ----------------
__device__ float g_x[NV * 3];
__device__ float g_nrm[NV * 3];
__device__ float g_cubes[(size_t)NV * 375];
__device__ float g_xl[(size_t)NV * 128];
__device__ float g_cat[(size_t)NV * 256];   // [:,0:128]=h1, [:,128:256]=lfc out
__device__ float g_h2[(size_t)NV * 512];
__device__ float g_h3[(size_t)NV * 256];
__device__ float g_delta[NV * 3];
__device__ float g_vol1[96 * 96 * 96];
__device__ float g_vol2[48 * 48 * 48];
__device__ float g_cnt[NV];
__device__ float g_agg[NV * 3];

// ---------------- utility kernels ----------------
__global__ void zero_kernel(float* p, int n) {
    int i = blockIdx.x * blockDim.x + threadIdx.x;
    if (i < n) p[i] = 0.f;
}

__global__ void copy_kernel(const float* __restrict__ a, float* __restrict__ b, int n) {
    int i = blockIdx.x * blockDim.x + threadIdx.x;
    if (i < n) b[i] = a[i];
}

// mean-pool 2x2x2: src is (2Ld)^3, dst is Ld^3
__global__ void downsample_kernel(const float* __restrict__ src, float* __restrict__ dst, int Ld) {
    int i = blockIdx.x * blockDim.x + threadIdx.x;
    int tot = Ld * Ld * Ld;
    if (i >= tot) return;
    int z = i % Ld;
    int y = (i / Ld) % Ld;
    int x = i / (Ld * Ld);
    int Ls = Ld * 2;
    const float* s = src + ((size_t)(2 * x) * Ls + (size_t)(2 * y)) * Ls + (size_t)(2 * z);
    float sum = 0.f;
#pragma unroll
    for (int a = 0; a < 2; a++)
#pragma unroll
        for (int b = 0; b < 2; b++)
#pragma unroll
            for (int c = 0; c < 2; c++)
                sum += s[((size_t)a * Ls + b) * Ls + c];
    dst[i] = sum * 0.125f;
}

// ---------------- vertex normals (face scatter) ----------------
__global__ void face_normal_kernel(const float* __restrict__ x, const int* __restrict__ f,
                                   float* __restrict__ nrm) {
    int i = blockIdx.x * blockDim.x + threadIdx.x;
    if (i >= NFACE) return;
    int i0 = f[3 * i], i1 = f[3 * i + 1], i2 = f[3 * i + 2];
    float v0x = x[3 * i0], v0y = x[3 * i0 + 1], v0z = x[3 * i0 + 2];
    float v1x = x[3 * i1], v1y = x[3 * i1 + 1], v1z = x[3 * i1 + 2];
    float v2x = x[3 * i2], v2y = x[3 * i2 + 1], v2z = x[3 * i2 + 2];
    float e1x = v1x - v0x, e1y = v1y - v0y, e1z = v1z - v0z;
    float e2x = v2x - v0x, e2y = v2y - v0y, e2z = v2z - v0z;
    float nx = e1y * e2z - e1z * e2y;
    float ny = e1z * e2x - e1x * e2z;
    float nz = e1x * e2y - e1y * e2x;
    atomicAdd(&nrm[3 * i0 + 0], nx); atomicAdd(&nrm[3 * i0 + 1], ny); atomicAdd(&nrm[3 * i0 + 2], nz);
    atomicAdd(&nrm[3 * i1 + 0], nx); atomicAdd(&nrm[3 * i1 + 1], ny); atomicAdd(&nrm[3 * i1 + 2], nz);
    atomicAdd(&nrm[3 * i2 + 0], nx); atomicAdd(&nrm[3 * i2 + 1], ny); atomicAdd(&nrm[3 * i2 + 2], nz);
}

// fc1: [x, n/|n|] (6) -> 128, lrelu, write into g_cat[:, 0:128]
__global__ void fc1_kernel(const float* __restrict__ x, const float* __restrict__ nrm,
                           const float* __restrict__ w, const float* __restrict__ b,
                           float* __restrict__ cat) {
    __shared__ float s_in[6];
    int v = blockIdx.x;
    int o = threadIdx.x;  // 128
    if (o == 0) {
        float nx = nrm[3 * v], ny = nrm[3 * v + 1], nz = nrm[3 * v + 2];
        float len = sqrtf(nx * nx + ny * ny + nz * nz);
        float inv = 1.f / fmaxf(len, 1e-12f);
        s_in[0] = x[3 * v]; s_in[1] = x[3 * v + 1]; s_in[2] = x[3 * v + 2];
        s_in[3] = nx * inv; s_in[4] = ny * inv; s_in[5] = nz * inv;
    }
    __syncthreads();
    float acc = b[o];
#pragma unroll
    for (int k = 0; k < 6; k++) acc += s_in[k] * w[o * 6 + k];
    cat[(size_t)v * 256 + o] = acc > 0.f ? acc : 0.15f * acc;
}

// ---------------- multiscale cube sampling: (N, 3*125) ----------------
__global__ void cube_sample_kernel(const float* __restrict__ x, const float* __restrict__ vol0,
                                   const float* __restrict__ vol1, const float* __restrict__ vol2,
                                   float* __restrict__ cubes) {
    int gw = (blockIdx.x * blockDim.x + threadIdx.x) >> 5;
    int lane = threadIdx.x & 31;
    if (gw >= NV) return;
    float px = x[3 * gw], py = x[3 * gw + 1], pz = x[3 * gw + 2];
#pragma unroll
    for (int n = 0; n < 3; n++) {
        const float* vol = (n == 0) ? vol0 : ((n == 1) ? vol1 : vol2);
        int Ln = 192 >> n;
        float mul = (float)(96 >> n);
        int ix = (int)rintf((px + 1.f) * mul);
        int iy = (int)rintf((py + 1.f) * mul);
        int iz = (int)rintf((pz + 1.f) * mul);
        int hi = Ln - 3;
        ix = min(max(ix, 2), hi);
        iy = min(max(iy, 2), hi);
        iz = min(max(iz, 2), hi);
        for (int j = lane; j < 125; j += 32) {
            int a = j / 25, r = j - 25 * a;
            int bb = r / 5, c = r - 5 * bb;
            int X = ix + a - 2, Y = iy + bb - 2, Z = iz + c - 2;
            cubes[(size_t)gw * 375 + n * 125 + j] = vol[((size_t)X * Ln + Y) * Ln + Z];
        }
    }
}

// ---------------- generic SGEMM: C[M,Nout] = A[M,K] * W[Nout,K]^T + bias ----------------
// ACT: 0 = none, 1 = leaky_relu(0.15)
template <int ACT>
__global__ void gemm_nt_kernel(const float* __restrict__ A, int lda,
                               const float* __restrict__ W,
                               const float* __restrict__ bias,
                               float* __restrict__ C, int ldc,
                               int M, int Nout, int K) {
    const int BM = 64, BN = 64, BK = 16;
    __shared__ float As[BK][BM + 4];
    __shared__ float Ws[BK][BN + 4];
    int tid = threadIdx.x;        // 256 threads
    int tr = tid >> 4, tc = tid & 15;
    int m0 = blockIdx.x * BM, n0 = blockIdx.y * BN;

    float acc[4][4] = {};
    for (int k0 = 0; k0 < K; k0 += BK) {
#pragma unroll
        for (int l = 0; l < 4; l++) {
            int idx = tid + l * 256;
            int r = idx >> 4, kk = idx & 15;
            int gr = m0 + r, gk = k0 + kk;
            As[kk][r] = (gr < M && gk < K) ? A[(size_t)gr * lda + gk] : 0.f;
            int gc = n0 + r;
            Ws[kk][r] = (gc < Nout && gk < K) ? W[(size_t)gc * K + gk] : 0.f;
        }
        __syncthreads();
#pragma unroll
        for (int k = 0; k < BK; k++) {
            float ra[4], rb[4];
#pragma unroll
            for (int i = 0; i < 4; i++) ra[i] = As[k][tr * 4 + i];
#pragma unroll
            for (int j = 0; j < 4; j++) rb[j] = Ws[k][tc * 4 + j];
#pragma unroll
            for (int i = 0; i < 4; i++)
#pragma unroll
                for (int j = 0; j < 4; j++) acc[i][j] += ra[i] * rb[j];
        }
        __syncthreads();
    }
#pragma unroll
    for (int i = 0; i < 4; i++) {
        int gr = m0 + tr * 4 + i;
        if (gr >= M) continue;
#pragma unroll
        for (int j = 0; j < 4; j++) {
            int gc = n0 + tc * 4 + j;
            if (gc >= Nout) continue;
            float v = acc[i][j] + bias[gc];
            if (ACT == 1) v = (v > 0.f) ? v : 0.15f * v;
            C[(size_t)gr * ldc + gc] = v;
        }
    }
}

__global__ void update_x_kernel(float* __restrict__ x, const float* __restrict__ delta, int n) {
    int i = blockIdx.x * blockDim.x + threadIdx.x;
    if (i < n) x[i] = x[i] + tanhf(delta[i]) * 0.1f;
}

// ---------------- smoothing ----------------
__global__ void edge_kernel(const float* __restrict__ x, const int* __restrict__ f,
                            float* __restrict__ agg, float* __restrict__ cnt) {
    int i = blockIdx.x * blockDim.x + threadIdx.x;
    if (i >= NFACE) return;
    int i0 = f[3 * i], i1 = f[3 * i + 1], i2 = f[3 * i + 2];
    atomicAdd(&cnt[i0], 1.f);
    atomicAdd(&cnt[i1], 1.f);
    atomicAdd(&cnt[i2], 1.f);
    // edges: i0->i1, i1->i2, i2->i0
#pragma unroll
    for (int c = 0; c < 3; c++) {
        atomicAdd(&agg[3 * i1 + c], x[3 * i0 + c]);
        atomicAdd(&agg[3 * i2 + c], x[3 * i1 + c]);
        atomicAdd(&agg[3 * i0 + c], x[3 * i2 + c]);
    }
}

__global__ void smooth_final_kernel(const float* __restrict__ agg, const float* __restrict__ cnt,
                                    float* __restrict__ out) {
    int v = blockIdx.x * blockDim.x + threadIdx.x;
    if (v >= NV) return;
    float c = fmaxf(cnt[v], 1.f);
    float inv = 1.f / c;
    out[3 * v + 0] = agg[3 * v + 0] * inv;
    out[3 * v + 1] = agg[3 * v + 1] * inv;
    out[3 * v + 2] = agg[3 * v + 2] * inv;
}

// ---------------- launcher ----------------
static inline int ceil_div(int a, int b) { return (a + b - 1) / b; }

extern "C" void kernel_launch(void* const* d_in, const int* in_sizes, int n_in,
                              void* d_out, int out_size) {
    const float* v      = (const float*)d_in[0];
    const int*   f      = (const int*)d_in[1];
    const float* volume = (const float*)d_in[2];
    const float* fc1_w  = (const float*)d_in[3];
    const float* fc1_b  = (const float*)d_in[4];
    const float* fc2_w  = (const float*)d_in[5];
    const float* fc2_b  = (const float*)d_in[6];
    const float* fc3_w  = (const float*)d_in[7];
    const float* fc3_b  = (const float*)d_in[8];
    const float* fc4_w  = (const float*)d_in[9];
    const float* fc4_b  = (const float*)d_in[10];
    const float* conv_w = (const float*)d_in[11];
    const float* conv_b = (const float*)d_in[12];
    const float* lfc_w  = (const float*)d_in[13];
    const float* lfc_b  = (const float*)d_in[14];
    float* out = (float*)d_out;

    float *px, *pnrm, *pcubes, *pxl, *pcat, *ph2, *ph3, *pdelta, *pvol1, *pvol2, *pcnt, *pagg;
    cudaGetSymbolAddress((void**)&px, g_x);
    cudaGetSymbolAddress((void**)&pnrm, g_nrm);
    cudaGetSymbolAddress((void**)&pcubes, g_cubes);
    cudaGetSymbolAddress((void**)&pxl, g_xl);
    cudaGetSymbolAddress((void**)&pcat, g_cat);
    cudaGetSymbolAddress((void**)&ph2, g_h2);
    cudaGetSymbolAddress((void**)&ph3, g_h3);
    cudaGetSymbolAddress((void**)&pdelta, g_delta);
    cudaGetSymbolAddress((void**)&pvol1, g_vol1);
    cudaGetSymbolAddress((void**)&pvol2, g_vol2);
    cudaGetSymbolAddress((void**)&pcnt, g_cnt);
    cudaGetSymbolAddress((void**)&pagg, g_agg);

    const int T = 256;
    const int MT = ceil_div(NV, 64);  // 2344 M-tiles

    // init x = v
    copy_kernel<<<ceil_div(NV * 3, T), T>>>(v, px, NV * 3);
    // downsampled volume pyramid (volume constant across blocks)
    downsample_kernel<<<ceil_div(96 * 96 * 96, T), T>>>(volume, pvol1, 96);
    downsample_kernel<<<ceil_div(48 * 48 * 48, T), T>>>(pvol1, pvol2, 48);

    for (int b = 0; b < 3; b++) {
        // vertex normals
        zero_kernel<<<ceil_div(NV * 3, T), T>>>(pnrm, NV * 3);
        face_normal_kernel<<<ceil_div(NFACE, T), T>>>(px, f, pnrm);
        // fc1 -> g_cat[:, 0:128]
        fc1_kernel<<<NV, 128>>>(px, pnrm, fc1_w + (size_t)b * 128 * 6, fc1_b + (size_t)b * 128, pcat);
        // cube sampling -> (N, 375)
        cube_sample_kernel<<<ceil_div(NV * 32, T), T>>>(px, volume, pvol1, pvol2, pcubes);
        // conv GEMM: (N,375) -> (N,128)
        gemm_nt_kernel<0><<<dim3(MT, 2), 256>>>(pcubes, 375, conv_w + (size_t)b * 128 * 375,
                                                conv_b + (size_t)b * 128, pxl, 128, NV, 128, 375);
        // lfc GEMM: (N,128) -> g_cat[:, 128:256]
        gemm_nt_kernel<0><<<dim3(MT, 2), 256>>>(pxl, 128, lfc_w + (size_t)b * 128 * 128,
                                                lfc_b + (size_t)b * 128, pcat + 128, 256, NV, 128, 128);
        // fc2: (N,256) -> (N,512), lrelu
        gemm_nt_kernel<1><<<dim3(MT, 8), 256>>>(pcat, 256, fc2_w + (size_t)b * 512 * 256,
                                                fc2_b + (size_t)b * 512, ph2, 512, NV, 512, 256);
        // fc3: (N,512) -> (N,256), lrelu
        gemm_nt_kernel<1><<<dim3(MT, 4), 256>>>(ph2, 512, fc3_w + (size_t)b * 256 * 512,
                                                fc3_b + (size_t)b * 256, ph3, 256, NV, 256, 512);
        // fc4: (N,256) -> (N,3)
        gemm_nt_kernel<0><<<dim3(MT, 1), 256>>>(ph3, 256, fc4_w + (size_t)b * 3 * 256,
                                                fc4_b + (size_t)b * 3, pdelta, 3, NV, 3, 256);
        // x = x + tanh(delta)*0.1
        update_x_kernel<<<ceil_div(NV * 3, T), T>>>(px, pdelta, NV * 3);
    }

    // one Laplacian smoothing pass (n_smooth fixed at 1 by setup_inputs)
    zero_kernel<<<ceil_div(NV, T), T>>>(pcnt, NV);
    zero_kernel<<<ceil_div(NV * 3, T), T>>>(pagg, NV * 3);
    edge_kernel<<<ceil_div(NFACE, T), T>>>(px, f, pagg, pcnt);
    smooth_final_kernel<<<ceil_div(NV, T), T>>>(pagg, pcnt, out);
}

// round 2
// speedup vs baseline: 2.2147x; 2.2147x over previous
#include <cuda_runtime.h>
#include <cuda_bf16.h>
#include <math.h>

#define NV    150000
#define NFACE 300000
typedef __nv_bfloat16 bf16;

// ---------------- scratch (device globals; no allocs allowed) ----------------
__device__ float g_x[NV * 3];
__device__ float g_nrm[NV * 3];
__device__ bf16  g_cubes_h[(size_t)NV * 384];
__device__ bf16  g_cubes_l[(size_t)NV * 384];
__device__ bf16  g_xl_h[(size_t)NV * 128];
__device__ bf16  g_xl_l[(size_t)NV * 128];
__device__ bf16  g_cat_h[(size_t)NV * 256];
__device__ bf16  g_cat_l[(size_t)NV * 256];
__device__ bf16  g_h2_h[(size_t)NV * 512];
__device__ bf16  g_h2_l[(size_t)NV * 512];
__device__ bf16  g_h3_h[(size_t)NV * 256];
__device__ bf16  g_h3_l[(size_t)NV * 256];
__device__ float g_vol1[96 * 96 * 96];
__device__ float g_vol2[48 * 48 * 48];
__device__ float g_cnt[NV];
__device__ float g_agg[NV * 3];
// pre-split weights
__device__ bf16 g_convw_h[3 * 128 * 384];
__device__ bf16 g_convw_l[3 * 128 * 384];
__device__ bf16 g_lfcw_h[3 * 128 * 128];
__device__ bf16 g_lfcw_l[3 * 128 * 128];
__device__ bf16 g_fc2w_h[3 * 512 * 256];
__device__ bf16 g_fc2w_l[3 * 512 * 256];
__device__ bf16 g_fc3w_h[3 * 256 * 512];
__device__ bf16 g_fc3w_l[3 * 256 * 512];

__device__ __forceinline__ void split_store(bf16* __restrict__ H, bf16* __restrict__ L,
                                            size_t idx, float v) {
    bf16 h = __float2bfloat16(v);
    H[idx] = h;
    L[idx] = __float2bfloat16(v - __bfloat162float(h));
}

// ---------------- utility kernels ----------------
__global__ void zero_kernel(float* p, int n) {
    int i = blockIdx.x * blockDim.x + threadIdx.x;
    if (i < n) p[i] = 0.f;
}
__global__ void copy_kernel(const float* __restrict__ a, float* __restrict__ b, int n) {
    int i = blockIdx.x * blockDim.x + threadIdx.x;
    if (i < n) b[i] = a[i];
}
__global__ void zero_pad_kernel() {
    int i = blockIdx.x * blockDim.x + threadIdx.x;
    if (i >= NV * 9) return;
    int v = i / 9, p = i - 9 * v;
    size_t idx = (size_t)v * 384 + 375 + p;
    g_cubes_h[idx] = __float2bfloat16(0.f);
    g_cubes_l[idx] = __float2bfloat16(0.f);
}
// generic fp32 -> split bf16
__global__ void split_weights_kernel(const float* __restrict__ src, bf16* __restrict__ h,
                                     bf16* __restrict__ l, int n) {
    int i = blockIdx.x * blockDim.x + threadIdx.x;
    if (i < n) split_store(h, l, i, src[i]);
}
// conv weights: [3][128][375] -> padded [3][128][384]
__global__ void split_conv_kernel(const float* __restrict__ src, bf16* __restrict__ h,
                                  bf16* __restrict__ l) {
    int i = blockIdx.x * blockDim.x + threadIdx.x;
    if (i >= 3 * 128 * 384) return;
    int k = i % 384;
    int row = i / 384;  // 0..383 rows of [3*128]
    float v = (k < 375) ? src[(size_t)row * 375 + k] : 0.f;
    split_store(h, l, i, v);
}

// mean-pool 2x2x2
__global__ void downsample_kernel(const float* __restrict__ src, float* __restrict__ dst, int Ld) {
    int i = blockIdx.x * blockDim.x + threadIdx.x;
    int tot = Ld * Ld * Ld;
    if (i >= tot) return;
    int z = i % Ld;
    int y = (i / Ld) % Ld;
    int x = i / (Ld * Ld);
    int Ls = Ld * 2;
    const float* s = src + ((size_t)(2 * x) * Ls + (size_t)(2 * y)) * Ls + (size_t)(2 * z);
    float sum = 0.f;
#pragma unroll
    for (int a = 0; a < 2; a++)
#pragma unroll
        for (int b = 0; b < 2; b++)
#pragma unroll
            for (int c = 0; c < 2; c++)
                sum += s[((size_t)a * Ls + b) * Ls + c];
    dst[i] = sum * 0.125f;
}

// ---------------- vertex normals (face scatter) ----------------
__global__ void face_normal_kernel(const float* __restrict__ x, const int* __restrict__ f,
                                   float* __restrict__ nrm) {
    int i = blockIdx.x * blockDim.x + threadIdx.x;
    if (i >= NFACE) return;
    int i0 = f[3 * i], i1 = f[3 * i + 1], i2 = f[3 * i + 2];
    float v0x = x[3 * i0], v0y = x[3 * i0 + 1], v0z = x[3 * i0 + 2];
    float v1x = x[3 * i1], v1y = x[3 * i1 + 1], v1z = x[3 * i1 + 2];
    float v2x = x[3 * i2], v2y = x[3 * i2 + 1], v2z = x[3 * i2 + 2];
    float e1x = v1x - v0x, e1y = v1y - v0y, e1z = v1z - v0z;
    float e2x = v2x - v0x, e2y = v2y - v0y, e2z = v2z - v0z;
    float nx = e1y * e2z - e1z * e2y;
    float ny = e1z * e2x - e1x * e2z;
    float nz = e1x * e2y - e1y * e2x;
    atomicAdd(&nrm[3 * i0 + 0], nx); atomicAdd(&nrm[3 * i0 + 1], ny); atomicAdd(&nrm[3 * i0 + 2], nz);
    atomicAdd(&nrm[3 * i1 + 0], nx); atomicAdd(&nrm[3 * i1 + 1], ny); atomicAdd(&nrm[3 * i1 + 2], nz);
    atomicAdd(&nrm[3 * i2 + 0], nx); atomicAdd(&nrm[3 * i2 + 1], ny); atomicAdd(&nrm[3 * i2 + 2], nz);
}

// fc1: [x, n/|n|] (6) -> 128, lrelu, split-write into cat[:, 0:128]
__global__ void fc1_kernel(const float* __restrict__ x, const float* __restrict__ nrm,
                           const float* __restrict__ w, const float* __restrict__ b,
                           bf16* __restrict__ cat_h, bf16* __restrict__ cat_l) {
    __shared__ float s_in[6];
    int v = blockIdx.x;
    int o = threadIdx.x;  // 128
    if (o == 0) {
        float nx = nrm[3 * v], ny = nrm[3 * v + 1], nz = nrm[3 * v + 2];
        float len = sqrtf(nx * nx + ny * ny + nz * nz);
        float inv = 1.f / fmaxf(len, 1e-12f);
        s_in[0] = x[3 * v]; s_in[1] = x[3 * v + 1]; s_in[2] = x[3 * v + 2];
        s_in[3] = nx * inv; s_in[4] = ny * inv; s_in[5] = nz * inv;
    }
    __syncthreads();
    float acc = b[o];
#pragma unroll
    for (int k = 0; k < 6; k++) acc += s_in[k] * w[o * 6 + k];
    acc = acc > 0.f ? acc : 0.15f * acc;
    split_store(cat_h, cat_l, (size_t)v * 256 + o, acc);
}

// ---------------- multiscale cube sampling, split-bf16 output (lda=384) ----------------
__global__ void cube_sample_kernel(const float* __restrict__ x, const float* __restrict__ vol0,
                                   const float* __restrict__ vol1, const float* __restrict__ vol2,
                                   bf16* __restrict__ ch, bf16* __restrict__ cl) {
    int gw = (blockIdx.x * blockDim.x + threadIdx.x) >> 5;
    int lane = threadIdx.x & 31;
    if (gw >= NV) return;
    float px = x[3 * gw], py = x[3 * gw + 1], pz = x[3 * gw + 2];
#pragma unroll
    for (int n = 0; n < 3; n++) {
        const float* vol = (n == 0) ? vol0 : ((n == 1) ? vol1 : vol2);
        int Ln = 192 >> n;
        float mul = (float)(96 >> n);
        int ix = (int)rintf((px + 1.f) * mul);
        int iy = (int)rintf((py + 1.f) * mul);
        int iz = (int)rintf((pz + 1.f) * mul);
        int hi = Ln - 3;
        ix = min(max(ix, 2), hi);
        iy = min(max(iy, 2), hi);
        iz = min(max(iz, 2), hi);
        for (int j = lane; j < 125; j += 32) {
            int a = j / 25, r = j - 25 * a;
            int bb = r / 5, c = r - 5 * bb;
            int X = ix + a - 2, Y = iy + bb - 2, Z = iz + c - 2;
            float val = vol[((size_t)X * Ln + Y) * Ln + Z];
            split_store(ch, cl, (size_t)gw * 384 + n * 125 + j, val);
        }
    }
}

// ---------------- split-bf16 MMA GEMM ----------------
// C[M,Nout] = A[M,K] @ W[Nout,K]^T + bias; A/W given as (hi, lo) bf16 planes.
// Requires: K % 32 == 0, Nout % 128 == 0, lda even.
// BM=64, BN=128, BK=32, 256 threads (8 warps: 2 m-warps x 4 n-warps, warp tile 32x32).
#define SAS 20  // smem row stride in u32 (= 40 bf16)

__device__ __forceinline__ void mma16816(float* d, const unsigned* a, const unsigned* b) {
    asm volatile(
        "mma.sync.aligned.m16n8k16.row.col.f32.bf16.bf16.f32 "
        "{%0,%1,%2,%3}, {%4,%5,%6,%7}, {%8,%9}, {%0,%1,%2,%3};\n"
        : "+f"(d[0]), "+f"(d[1]), "+f"(d[2]), "+f"(d[3])
        : "r"(a[0]), "r"(a[1]), "r"(a[2]), "r"(a[3]), "r"(b[0]), "r"(b[1]));
}

template <int ACT>  // 0 none, 1 lrelu(0.15)
__global__ __launch_bounds__(256, 2) void gemm_mma_kernel(
    const bf16* __restrict__ Ah, const bf16* __restrict__ Al, int lda,
    const bf16* __restrict__ Wh, const bf16* __restrict__ Wl,
    const float* __restrict__ bias,
    bf16* __restrict__ Ch, bf16* __restrict__ Cl, int ldc,
    int M, int K) {
    __shared__ unsigned sA[2][64 * SAS];
    __shared__ unsigned sW[2][128 * SAS];
    int tid = threadIdx.x;
    int wid = tid >> 5, lane = tid & 31;
    int wm = wid & 1, wn = wid >> 1;
    int g = lane >> 2, tg = lane & 3;
    int m0 = blockIdx.x * 64;
    int n0 = blockIdx.y * 128;
    const unsigned* Ah32 = (const unsigned*)Ah;
    const unsigned* Al32 = (const unsigned*)Al;
    const unsigned* Wh32 = (const unsigned*)Wh;
    const unsigned* Wl32 = (const unsigned*)Wl;

    float acc[2][4][4];
#pragma unroll
    for (int i = 0; i < 2; i++)
#pragma unroll
        for (int j = 0; j < 4; j++)
#pragma unroll
            for (int k = 0; k < 4; k++) acc[i][j][k] = 0.f;

    for (int k0 = 0; k0 < K; k0 += 32) {
        // load A tile: 64 rows x 16 u32
#pragma unroll
        for (int l = 0; l < 4; l++) {
            int idx = tid + l * 256;
            int r = idx >> 4, kp = idx & 15;
            int gr = m0 + r;
            unsigned vh = 0u, vl = 0u;
            if (gr < M) {
                size_t off = (((size_t)gr * lda + k0) >> 1) + kp;
                vh = Ah32[off];
                vl = Al32[off];
            }
            sA[0][r * SAS + kp] = vh;
            sA[1][r * SAS + kp] = vl;
        }
        // load W tile: 128 rows x 16 u32
#pragma unroll
        for (int l = 0; l < 8; l++) {
            int idx = tid + l * 256;
            int r = idx >> 4, kp = idx & 15;
            size_t off = (((size_t)(n0 + r) * K + k0) >> 1) + kp;
            sW[0][r * SAS + kp] = Wh32[off];
            sW[1][r * SAS + kp] = Wl32[off];
        }
        __syncthreads();
#pragma unroll
        for (int ks = 0; ks < 2; ks++) {
            int kw = ks * 8;
            unsigned ah[2][4], al[2][4];
#pragma unroll
            for (int fm = 0; fm < 2; fm++) {
                int rb = wm * 32 + fm * 16;
                int r0 = (rb + g) * SAS + kw + tg;
                int r1 = (rb + g + 8) * SAS + kw + tg;
                ah[fm][0] = sA[0][r0];     ah[fm][1] = sA[0][r1];
                ah[fm][2] = sA[0][r0 + 4]; ah[fm][3] = sA[0][r1 + 4];
                al[fm][0] = sA[1][r0];     al[fm][1] = sA[1][r1];
                al[fm][2] = sA[1][r0 + 4]; al[fm][3] = sA[1][r1 + 4];
            }
#pragma unroll
            for (int ch = 0; ch < 4; ch++) {
                int nb = (wn * 32 + ch * 8 + g) * SAS + kw + tg;
                unsigned bh[2] = {sW[0][nb], sW[0][nb + 4]};
                unsigned bl[2] = {sW[1][nb], sW[1][nb + 4]};
#pragma unroll
                for (int fm = 0; fm < 2; fm++) {
                    mma16816(acc[fm][ch], ah[fm], bh);
                    mma16816(acc[fm][ch], ah[fm], bl);
                    mma16816(acc[fm][ch], al[fm], bh);
                }
            }
        }
        __syncthreads();
    }
    // epilogue
#pragma unroll
    for (int fm = 0; fm < 2; fm++) {
        int r0 = m0 + wm * 32 + fm * 16 + g;
#pragma unroll
        for (int ch = 0; ch < 4; ch++) {
            int c0 = n0 + wn * 32 + ch * 8 + 2 * tg;
            float b0 = bias[c0], b1 = bias[c0 + 1];
#pragma unroll
            for (int half = 0; half < 2; half++) {
                int gr = r0 + half * 8;
                if (gr >= M) continue;
                float v0 = acc[fm][ch][half * 2 + 0] + b0;
                float v1 = acc[fm][ch][half * 2 + 1] + b1;
                if (ACT == 1) {
                    v0 = v0 > 0.f ? v0 : 0.15f * v0;
                    v1 = v1 > 0.f ? v1 : 0.15f * v1;
                }
                split_store(Ch, Cl, (size_t)gr * ldc + c0, v0);
                split_store(Ch, Cl, (size_t)gr * ldc + c0 + 1, v1);
            }
        }
    }
}

// fc4 + tanh update fused: warp per vertex, K=256, 3 outputs
__global__ void fc4_update_kernel(const bf16* __restrict__ h3h, const bf16* __restrict__ h3l,
                                  const float* __restrict__ w, const float* __restrict__ b,
                                  float* __restrict__ x) {
    int gw = (blockIdx.x * blockDim.x + threadIdx.x) >> 5;
    int lane = threadIdx.x & 31;
    if (gw >= NV) return;
    float s0 = 0.f, s1 = 0.f, s2 = 0.f;
    size_t base = (size_t)gw * 256;
#pragma unroll
    for (int k = lane; k < 256; k += 32) {
        float a = __bfloat162float(h3h[base + k]) + __bfloat162float(h3l[base + k]);
        s0 += a * w[k];
        s1 += a * w[256 + k];
        s2 += a * w[512 + k];
    }
#pragma unroll
    for (int off = 16; off > 0; off >>= 1) {
        s0 += __shfl_xor_sync(0xFFFFFFFFu, s0, off);
        s1 += __shfl_xor_sync(0xFFFFFFFFu, s1, off);
        s2 += __shfl_xor_sync(0xFFFFFFFFu, s2, off);
    }
    if (lane == 0) {
        x[3 * gw + 0] += tanhf(s0 + b[0]) * 0.1f;
        x[3 * gw + 1] += tanhf(s1 + b[1]) * 0.1f;
        x[3 * gw + 2] += tanhf(s2 + b[2]) * 0.1f;
    }
}

// ---------------- smoothing ----------------
__global__ void edge_kernel(const float* __restrict__ x, const int* __restrict__ f,
                            float* __restrict__ agg, float* __restrict__ cnt) {
    int i = blockIdx.x * blockDim.x + threadIdx.x;
    if (i >= NFACE) return;
    int i0 = f[3 * i], i1 = f[3 * i + 1], i2 = f[3 * i + 2];
    atomicAdd(&cnt[i0], 1.f);
    atomicAdd(&cnt[i1], 1.f);
    atomicAdd(&cnt[i2], 1.f);
#pragma unroll
    for (int c = 0; c < 3; c++) {
        atomicAdd(&agg[3 * i1 + c], x[3 * i0 + c]);
        atomicAdd(&agg[3 * i2 + c], x[3 * i1 + c]);
        atomicAdd(&agg[3 * i0 + c], x[3 * i2 + c]);
    }
}

__global__ void smooth_final_kernel(const float* __restrict__ agg, const float* __restrict__ cnt,
                                    float* __restrict__ out) {
    int v = blockIdx.x * blockDim.x + threadIdx.x;
    if (v >= NV) return;
    float c = fmaxf(cnt[v], 1.f);
    float inv = 1.f / c;
    out[3 * v + 0] = agg[3 * v + 0] * inv;
    out[3 * v + 1] = agg[3 * v + 1] * inv;
    out[3 * v + 2] = agg[3 * v + 2] * inv;
}

// ---------------- launcher ----------------
static inline int ceil_div(int a, int b) { return (a + b - 1) / b; }

extern "C" void kernel_launch(void* const* d_in, const int* in_sizes, int n_in,
                              void* d_out, int out_size) {
    const float* v      = (const float*)d_in[0];
    const int*   f      = (const int*)d_in[1];
    const float* volume = (const float*)d_in[2];
    const float* fc1_w  = (const float*)d_in[3];
    const float* fc1_b  = (const float*)d_in[4];
    const float* fc2_w  = (const float*)d_in[5];
    const float* fc2_b  = (const float*)d_in[6];
    const float* fc3_w  = (const float*)d_in[7];
    const float* fc3_b  = (const float*)d_in[8];
    const float* fc4_w  = (const float*)d_in[9];
    const float* fc4_b  = (const float*)d_in[10];
    const float* conv_w = (const float*)d_in[11];
    const float* conv_b = (const float*)d_in[12];
    const float* lfc_w  = (const float*)d_in[13];
    const float* lfc_b  = (const float*)d_in[14];
    float* out = (float*)d_out;

    float *px, *pnrm, *pvol1, *pvol2, *pcnt, *pagg;
    bf16 *pcub_h, *pcub_l, *pxl_h, *pxl_l, *pcat_h, *pcat_l, *ph2_h, *ph2_l, *ph3_h, *ph3_l;
    bf16 *pconvw_h, *pconvw_l, *plfcw_h, *plfcw_l, *pfc2w_h, *pfc2w_l, *pfc3w_h, *pfc3w_l;
    cudaGetSymbolAddress((void**)&px, g_x);
    cudaGetSymbolAddress((void**)&pnrm, g_nrm);
    cudaGetSymbolAddress((void**)&pvol1, g_vol1);
    cudaGetSymbolAddress((void**)&pvol2, g_vol2);
    cudaGetSymbolAddress((void**)&pcnt, g_cnt);
    cudaGetSymbolAddress((void**)&pagg, g_agg);
    cudaGetSymbolAddress((void**)&pcub_h, g_cubes_h);
    cudaGetSymbolAddress((void**)&pcub_l, g_cubes_l);
    cudaGetSymbolAddress((void**)&pxl_h, g_xl_h);
    cudaGetSymbolAddress((void**)&pxl_l, g_xl_l);
    cudaGetSymbolAddress((void**)&pcat_h, g_cat_h);
    cudaGetSymbolAddress((void**)&pcat_l, g_cat_l);
    cudaGetSymbolAddress((void**)&ph2_h, g_h2_h);
    cudaGetSymbolAddress((void**)&ph2_l, g_h2_l);
    cudaGetSymbolAddress((void**)&ph3_h, g_h3_h);
    cudaGetSymbolAddress((void**)&ph3_l, g_h3_l);
    cudaGetSymbolAddress((void**)&pconvw_h, g_convw_h);
    cudaGetSymbolAddress((void**)&pconvw_l, g_convw_l);
    cudaGetSymbolAddress((void**)&plfcw_h, g_lfcw_h);
    cudaGetSymbolAddress((void**)&plfcw_l, g_lfcw_l);
    cudaGetSymbolAddress((void**)&pfc2w_h, g_fc2w_h);
    cudaGetSymbolAddress((void**)&pfc2w_l, g_fc2w_l);
    cudaGetSymbolAddress((void**)&pfc3w_h, g_fc3w_h);
    cudaGetSymbolAddress((void**)&pfc3w_l, g_fc3w_l);

    const int T = 256;
    const int MT = ceil_div(NV, 64);  // 2344 M-tiles

    // init x = v ; volume pyramid ; pre-split weights ; zero conv-K pad
    copy_kernel<<<ceil_div(NV * 3, T), T>>>(v, px, NV * 3);
    downsample_kernel<<<ceil_div(96 * 96 * 96, T), T>>>(volume, pvol1, 96);
    downsample_kernel<<<ceil_div(48 * 48 * 48, T), T>>>(pvol1, pvol2, 48);
    split_conv_kernel<<<ceil_div(3 * 128 * 384, T), T>>>(conv_w, pconvw_h, pconvw_l);
    split_weights_kernel<<<ceil_div(3 * 128 * 128, T), T>>>(lfc_w, plfcw_h, plfcw_l, 3 * 128 * 128);
    split_weights_kernel<<<ceil_div(3 * 512 * 256, T), T>>>(fc2_w, pfc2w_h, pfc2w_l, 3 * 512 * 256);
    split_weights_kernel<<<ceil_div(3 * 256 * 512, T), T>>>(fc3_w, pfc3w_h, pfc3w_l, 3 * 256 * 512);
    zero_pad_kernel<<<ceil_div(NV * 9, T), T>>>();

    for (int b = 0; b < 3; b++) {
        zero_kernel<<<ceil_div(NV * 3, T), T>>>(pnrm, NV * 3);
        face_normal_kernel<<<ceil_div(NFACE, T), T>>>(px, f, pnrm);
        fc1_kernel<<<NV, 128>>>(px, pnrm, fc1_w + (size_t)b * 128 * 6, fc1_b + (size_t)b * 128,
                                pcat_h, pcat_l);
        cube_sample_kernel<<<ceil_div(NV * 32, T), T>>>(px, volume, pvol1, pvol2, pcub_h, pcub_l);
        // conv: (N,384) -> (N,128)
        gemm_mma_kernel<0><<<dim3(MT, 1), 256>>>(
            pcub_h, pcub_l, 384,
            pconvw_h + (size_t)b * 128 * 384, pconvw_l + (size_t)b * 128 * 384,
            conv_b + (size_t)b * 128, pxl_h, pxl_l, 128, NV, 384);
        // lfc: (N,128) -> cat[:,128:256]
        gemm_mma_kernel<0><<<dim3(MT, 1), 256>>>(
            pxl_h, pxl_l, 128,
            plfcw_h + (size_t)b * 128 * 128, plfcw_l + (size_t)b * 128 * 128,
            lfc_b + (size_t)b * 128, pcat_h + 128, pcat_l + 128, 256, NV, 128);
        // fc2: (N,256) -> (N,512), lrelu
        gemm_mma_kernel<1><<<dim3(MT, 4), 256>>>(
            pcat_h, pcat_l, 256,
            pfc2w_h + (size_t)b * 512 * 256, pfc2w_l + (size_t)b * 512 * 256,
            fc2_b + (size_t)b * 512, ph2_h, ph2_l, 512, NV, 256);
        // fc3: (N,512) -> (N,256), lrelu
        gemm_mma_kernel<1><<<dim3(MT, 2), 256>>>(
            ph2_h, ph2_l, 512,
            pfc3w_h + (size_t)b * 256 * 512, pfc3w_l + (size_t)b * 256 * 512,
            fc3_b + (size_t)b * 256, ph3_h, ph3_l, 256, NV, 512);
        // fc4 + update
        fc4_update_kernel<<<ceil_div(NV * 32, T), T>>>(
            ph3_h, ph3_l, fc4_w + (size_t)b * 3 * 256, fc4_b + (size_t)b * 3, px);
    }

    // one Laplacian smoothing pass (n_smooth fixed at 1 by setup_inputs)
    zero_kernel<<<ceil_div(NV, T), T>>>(pcnt, NV);
    zero_kernel<<<ceil_div(NV * 3, T), T>>>(pagg, NV * 3);
    edge_kernel<<<ceil_div(NFACE, T), T>>>(px, f, pagg, pcnt);
    smooth_final_kernel<<<ceil_div(NV, T), T>>>(pagg, pcnt, out);
}

// round 3
// speedup vs baseline: 3.8832x; 1.7534x over previous
#include <cuda_runtime.h>
#include <cuda_bf16.h>
#include <math.h>

#define NV    150000
#define NFACE 300000
typedef __nv_bfloat16 bf16;

// ---------------- scratch (device globals; no allocs allowed) ----------------
__device__ float g_x[NV * 3];
__device__ float g_nrm[NV * 3];
__device__ bf16  g_cubes_h[(size_t)NV * 384];
__device__ bf16  g_cubes_l[(size_t)NV * 384];
__device__ bf16  g_cat_h[(size_t)NV * 256];    // [:,0:128]=h1, [:,128:256]=conv+lfc out
__device__ bf16  g_cat_l[(size_t)NV * 256];
__device__ bf16  g_h2_h[(size_t)NV * 512];
__device__ bf16  g_h2_l[(size_t)NV * 512];
__device__ bf16  g_h3_h[(size_t)NV * 256];
__device__ bf16  g_h3_l[(size_t)NV * 256];
__device__ float g_vol1[96 * 96 * 96];
__device__ float g_vol2[48 * 48 * 48];
__device__ float g_cnt[NV];
__device__ float g_agg[NV * 3];
// pre-split weights (conv fused with lfc: W' = lfc_w @ conv_w, padded K 375->384)
__device__ bf16  g_convw_h[3 * 128 * 384];
__device__ bf16  g_convw_l[3 * 128 * 384];
__device__ float g_convb[3 * 128];
__device__ bf16  g_fc2w_h[3 * 512 * 256];
__device__ bf16  g_fc2w_l[3 * 512 * 256];
__device__ bf16  g_fc3w_h[3 * 256 * 512];
__device__ bf16  g_fc3w_l[3 * 256 * 512];

__device__ __forceinline__ void split_store(bf16* __restrict__ H, bf16* __restrict__ L,
                                            size_t idx, float v) {
    bf16 h = __float2bfloat16(v);
    H[idx] = h;
    L[idx] = __float2bfloat16(v - __bfloat162float(h));
}

// ---------------- utility kernels ----------------
__global__ void zero_kernel(float* p, int n) {
    int i = blockIdx.x * blockDim.x + threadIdx.x;
    if (i < n) p[i] = 0.f;
}
__global__ void copy_kernel(const float* __restrict__ a, float* __restrict__ b, int n) {
    int i = blockIdx.x * blockDim.x + threadIdx.x;
    if (i < n) b[i] = a[i];
}
__global__ void zero_pad_kernel() {
    int i = blockIdx.x * blockDim.x + threadIdx.x;
    if (i >= NV * 9) return;
    int v = i / 9, p = i - 9 * v;
    size_t idx = (size_t)v * 384 + 375 + p;
    g_cubes_h[idx] = __float2bfloat16(0.f);
    g_cubes_l[idx] = __float2bfloat16(0.f);
}
__global__ void split_weights_kernel(const float* __restrict__ src, bf16* __restrict__ h,
                                     bf16* __restrict__ l, int n) {
    int i = blockIdx.x * blockDim.x + threadIdx.x;
    if (i < n) split_store(h, l, i, src[i]);
}
// W' = lfc_w @ conv_w  (per block), fp32 accum, split-stored, K padded to 384
__global__ void fuse_conv_lfc_w_kernel(const float* __restrict__ conv_w,
                                       const float* __restrict__ lfc_w,
                                       bf16* __restrict__ wh, bf16* __restrict__ wl) {
    int i = blockIdx.x * blockDim.x + threadIdx.x;
    if (i >= 3 * 128 * 384) return;
    int k = i % 384;
    int o = (i / 384) % 128;
    int b = i / (384 * 128);
    float s = 0.f;
    if (k < 375) {
        const float* lw = lfc_w + (size_t)b * 128 * 128 + (size_t)o * 128;
        const float* cw = conv_w + (size_t)b * 128 * 375 + k;
#pragma unroll 4
        for (int j = 0; j < 128; j++) s += lw[j] * cw[(size_t)j * 375];
    }
    split_store(wh, wl, i, s);
}
// b' = lfc_w @ conv_b + lfc_b
__global__ void fuse_conv_lfc_b_kernel(const float* __restrict__ conv_b,
                                       const float* __restrict__ lfc_w,
                                       const float* __restrict__ lfc_b,
                                       float* __restrict__ bout) {
    int i = blockIdx.x * blockDim.x + threadIdx.x;
    if (i >= 3 * 128) return;
    int o = i % 128, b = i / 128;
    float s = lfc_b[(size_t)b * 128 + o];
    const float* lw = lfc_w + (size_t)b * 128 * 128 + (size_t)o * 128;
    const float* cb = conv_b + (size_t)b * 128;
    for (int j = 0; j < 128; j++) s += lw[j] * cb[j];
    bout[i] = s;
}

// mean-pool 2x2x2
__global__ void downsample_kernel(const float* __restrict__ src, float* __restrict__ dst, int Ld) {
    int i = blockIdx.x * blockDim.x + threadIdx.x;
    int tot = Ld * Ld * Ld;
    if (i >= tot) return;
    int z = i % Ld;
    int y = (i / Ld) % Ld;
    int x = i / (Ld * Ld);
    int Ls = Ld * 2;
    const float* s = src + ((size_t)(2 * x) * Ls + (size_t)(2 * y)) * Ls + (size_t)(2 * z);
    float sum = 0.f;
#pragma unroll
    for (int a = 0; a < 2; a++)
#pragma unroll
        for (int b = 0; b < 2; b++)
#pragma unroll
            for (int c = 0; c < 2; c++)
                sum += s[((size_t)a * Ls + b) * Ls + c];
    dst[i] = sum * 0.125f;
}

// ---------------- vertex normals (face scatter) ----------------
__global__ void face_normal_kernel(const float* __restrict__ x, const int* __restrict__ f,
                                   float* __restrict__ nrm) {
    int i = blockIdx.x * blockDim.x + threadIdx.x;
    if (i >= NFACE) return;
    int i0 = f[3 * i], i1 = f[3 * i + 1], i2 = f[3 * i + 2];
    float v0x = x[3 * i0], v0y = x[3 * i0 + 1], v0z = x[3 * i0 + 2];
    float v1x = x[3 * i1], v1y = x[3 * i1 + 1], v1z = x[3 * i1 + 2];
    float v2x = x[3 * i2], v2y = x[3 * i2 + 1], v2z = x[3 * i2 + 2];
    float e1x = v1x - v0x, e1y = v1y - v0y, e1z = v1z - v0z;
    float e2x = v2x - v0x, e2y = v2y - v0y, e2z = v2z - v0z;
    float nx = e1y * e2z - e1z * e2y;
    float ny = e1z * e2x - e1x * e2z;
    float nz = e1x * e2y - e1y * e2x;
    atomicAdd(&nrm[3 * i0 + 0], nx); atomicAdd(&nrm[3 * i0 + 1], ny); atomicAdd(&nrm[3 * i0 + 2], nz);
    atomicAdd(&nrm[3 * i1 + 0], nx); atomicAdd(&nrm[3 * i1 + 1], ny); atomicAdd(&nrm[3 * i1 + 2], nz);
    atomicAdd(&nrm[3 * i2 + 0], nx); atomicAdd(&nrm[3 * i2 + 1], ny); atomicAdd(&nrm[3 * i2 + 2], nz);
}

// fc1: [x, n/|n|] (6) -> 128, lrelu, split-write into cat[:, 0:128]
// 128 threads, 8 vertices per block, weights cached in smem
__global__ void fc1_kernel(const float* __restrict__ x, const float* __restrict__ nrm,
                           const float* __restrict__ w, const float* __restrict__ b,
                           bf16* __restrict__ cat_h, bf16* __restrict__ cat_l) {
    __shared__ float sw[128 * 6];
    __shared__ float sb[128];
    __shared__ float sin_[8][6];
    int o = threadIdx.x;
#pragma unroll
    for (int j = o; j < 768; j += 128) sw[j] = w[j];
    sb[o] = b[o];
    int v0 = blockIdx.x * 8;
    if (o < 8) {
        int v = v0 + o;
        if (v < NV) {
            float nx = nrm[3 * v], ny = nrm[3 * v + 1], nz = nrm[3 * v + 2];
            float len = sqrtf(nx * nx + ny * ny + nz * nz);
            float inv = 1.f / fmaxf(len, 1e-12f);
            sin_[o][0] = x[3 * v]; sin_[o][1] = x[3 * v + 1]; sin_[o][2] = x[3 * v + 2];
            sin_[o][3] = nx * inv; sin_[o][4] = ny * inv; sin_[o][5] = nz * inv;
        }
    }
    __syncthreads();
#pragma unroll
    for (int t = 0; t < 8; t++) {
        int v = v0 + t;
        if (v >= NV) break;
        float acc = sb[o];
#pragma unroll
        for (int k = 0; k < 6; k++) acc += sin_[t][k] * sw[o * 6 + k];
        acc = acc > 0.f ? acc : 0.15f * acc;
        split_store(cat_h, cat_l, (size_t)v * 256 + o, acc);
    }
}

// ---------------- multiscale cube sampling, split-bf16 output (lda=384) ----------------
__global__ void cube_sample_kernel(const float* __restrict__ x, const float* __restrict__ vol0,
                                   const float* __restrict__ vol1, const float* __restrict__ vol2,
                                   bf16* __restrict__ ch, bf16* __restrict__ cl) {
    int gw = (blockIdx.x * blockDim.x + threadIdx.x) >> 5;
    int lane = threadIdx.x & 31;
    if (gw >= NV) return;
    float px = x[3 * gw], py = x[3 * gw + 1], pz = x[3 * gw + 2];
#pragma unroll
    for (int n = 0; n < 3; n++) {
        const float* vol = (n == 0) ? vol0 : ((n == 1) ? vol1 : vol2);
        int Ln = 192 >> n;
        float mul = (float)(96 >> n);
        int ix = (int)rintf((px + 1.f) * mul);
        int iy = (int)rintf((py + 1.f) * mul);
        int iz = (int)rintf((pz + 1.f) * mul);
        int hi = Ln - 3;
        ix = min(max(ix, 2), hi);
        iy = min(max(iy, 2), hi);
        iz = min(max(iz, 2), hi);
        for (int j = lane; j < 125; j += 32) {
            int a = j / 25, r = j - 25 * a;
            int bb = r / 5, c = r - 5 * bb;
            int X = ix + a - 2, Y = iy + bb - 2, Z = iz + c - 2;
            float val = vol[((size_t)X * Ln + Y) * Ln + Z];
            split_store(ch, cl, (size_t)gw * 384 + n * 125 + j, val);
        }
    }
}

// ---------------- pipelined split-bf16 MMA GEMM ----------------
// C[M,Nout] = A[M,K] @ W[Nout,K]^T + bias; A/W as (hi,lo) bf16 planes.
// BM=128, BN=128, BK=32, 256 threads (8 warps: 2m x 4n, warp tile 64x32).
// 2-stage cp.async pipeline, 80KB dynamic smem.
#define SAS   20                    // smem row stride in u32 (64B data + 16B pad)
#define PLANE (128 * SAS)           // u32 per plane
#define STAGE (4 * PLANE)           // u32 per stage (Ah, Al, Wh, Wl)

__device__ __forceinline__ void mma16816(float* d, const unsigned* a, const unsigned* b) {
    asm volatile(
        "mma.sync.aligned.m16n8k16.row.col.f32.bf16.bf16.f32 "
        "{%0,%1,%2,%3}, {%4,%5,%6,%7}, {%8,%9}, {%0,%1,%2,%3};\n"
        : "+f"(d[0]), "+f"(d[1]), "+f"(d[2]), "+f"(d[3])
        : "r"(a[0]), "r"(a[1]), "r"(a[2]), "r"(a[3]), "r"(b[0]), "r"(b[1]));
}
__device__ __forceinline__ void cp16(unsigned dst, const void* src, int sz) {
    asm volatile("cp.async.cg.shared.global [%0], [%1], 16, %2;\n"
                 :: "r"(dst), "l"(src), "r"(sz));
}
__device__ __forceinline__ void cp_commit() { asm volatile("cp.async.commit_group;\n"); }
template <int N>
__device__ __forceinline__ void cp_wait() { asm volatile("cp.async.wait_group %0;\n" :: "n"(N)); }

extern __shared__ unsigned dynsmem[];

__device__ __forceinline__ void load_tiles(unsigned sbase,  // smem byte addr of stage
                                           const bf16* __restrict__ Ah, const bf16* __restrict__ Al,
                                           const bf16* __restrict__ Wh, const bf16* __restrict__ Wl,
                                           int m0, int n0, int k0, int lda, int K, int M, int tid) {
#pragma unroll
    for (int l = 0; l < 2; l++) {
        int idx = tid + l * 256;
        int row = idx >> 2, q = idx & 3;
        // A: rows need M guard
        int gr = m0 + row;
        int sz = gr < M ? 16 : 0;
        int grc = gr < M ? gr : (M - 1);
        size_t offA = (size_t)grc * lda + k0 + q * 8;
        unsigned d = sbase + (unsigned)(row * SAS + q * 4) * 4u;
        cp16(d, Ah + offA, sz);
        cp16(d + PLANE * 4u, Al + offA, sz);
        // W: always in range
        size_t offW = (size_t)(n0 + row) * K + k0 + q * 8;
        cp16(d + 2u * PLANE * 4u, Wh + offW, 16);
        cp16(d + 3u * PLANE * 4u, Wl + offW, 16);
    }
    cp_commit();
}

template <int ACT>  // 0 none, 1 lrelu(0.15)
__global__ __launch_bounds__(256, 2) void gemm_mma_kernel(
    const bf16* __restrict__ Ah, const bf16* __restrict__ Al, int lda,
    const bf16* __restrict__ Wh, const bf16* __restrict__ Wl,
    const float* __restrict__ bias,
    bf16* __restrict__ Ch, bf16* __restrict__ Cl, int ldc,
    int M, int K) {
    int tid = threadIdx.x;
    int wid = tid >> 5, lane = tid & 31;
    int wm = wid & 1, wn = wid >> 1;       // 2 m-warps x 4 n-warps
    int g = lane >> 2, tg = lane & 3;
    int m0 = blockIdx.x * 128;
    int n0 = blockIdx.y * 128;

    unsigned smem_addr = (unsigned)__cvta_generic_to_shared(dynsmem);

    float acc[4][4][4];
#pragma unroll
    for (int i = 0; i < 4; i++)
#pragma unroll
        for (int j = 0; j < 4; j++)
#pragma unroll
            for (int k = 0; k < 4; k++) acc[i][j][k] = 0.f;

    int nIter = K >> 5;
    // prologue: stage 0
    load_tiles(smem_addr, Ah, Al, Wh, Wl, m0, n0, 0, lda, K, M, tid);

    for (int it = 0; it < nIter; it++) {
        if (it + 1 < nIter) {
            load_tiles(smem_addr + ((it + 1) & 1) * (STAGE * 4u),
                       Ah, Al, Wh, Wl, m0, n0, (it + 1) << 5, lda, K, M, tid);
            cp_wait<1>();
        } else {
            cp_wait<0>();
        }
        __syncthreads();

        const unsigned* s = dynsmem + (it & 1) * STAGE;
        const unsigned* sAh = s;
        const unsigned* sAl = s + PLANE;
        const unsigned* sWh = s + 2 * PLANE;
        const unsigned* sWl = s + 3 * PLANE;

#pragma unroll
        for (int ks = 0; ks < 2; ks++) {
            int kw = ks * 8;
            unsigned ah[4][4], al[4][4];
#pragma unroll
            for (int fm = 0; fm < 4; fm++) {
                int rb = wm * 64 + fm * 16;
                int r0 = (rb + g) * SAS + kw + tg;
                int r1 = (rb + g + 8) * SAS + kw + tg;
                ah[fm][0] = sAh[r0];     ah[fm][1] = sAh[r1];
                ah[fm][2] = sAh[r0 + 4]; ah[fm][3] = sAh[r1 + 4];
                al[fm][0] = sAl[r0];     al[fm][1] = sAl[r1];
                al[fm][2] = sAl[r0 + 4]; al[fm][3] = sAl[r1 + 4];
            }
#pragma unroll
            for (int ch = 0; ch < 4; ch++) {
                int nb = (wn * 32 + ch * 8 + g) * SAS + kw + tg;
                unsigned bh[2] = {sWh[nb], sWh[nb + 4]};
                unsigned bl[2] = {sWl[nb], sWl[nb + 4]};
#pragma unroll
                for (int fm = 0; fm < 4; fm++) {
                    mma16816(acc[fm][ch], ah[fm], bh);
                    mma16816(acc[fm][ch], ah[fm], bl);
                    mma16816(acc[fm][ch], al[fm], bh);
                }
            }
        }
        __syncthreads();
    }

    // epilogue: packed bf16x2 stores
#pragma unroll
    for (int fm = 0; fm < 4; fm++) {
        int r0 = m0 + wm * 64 + fm * 16 + g;
#pragma unroll
        for (int ch = 0; ch < 4; ch++) {
            int c0 = n0 + wn * 32 + ch * 8 + 2 * tg;
            float b0 = bias[c0], b1 = bias[c0 + 1];
#pragma unroll
            for (int half = 0; half < 2; half++) {
                int gr = r0 + half * 8;
                if (gr >= M) continue;
                float v0 = acc[fm][ch][half * 2 + 0] + b0;
                float v1 = acc[fm][ch][half * 2 + 1] + b1;
                if (ACT == 1) {
                    v0 = v0 > 0.f ? v0 : 0.15f * v0;
                    v1 = v1 > 0.f ? v1 : 0.15f * v1;
                }
                bf16 h0 = __float2bfloat16(v0);
                bf16 h1 = __float2bfloat16(v1);
                bf16 l0 = __float2bfloat16(v0 - __bfloat162float(h0));
                bf16 l1 = __float2bfloat16(v1 - __bfloat162float(h1));
                size_t off = (size_t)gr * ldc + c0;
                *(__nv_bfloat162*)(Ch + off) = __nv_bfloat162(h0, h1);
                *(__nv_bfloat162*)(Cl + off) = __nv_bfloat162(l0, l1);
            }
        }
    }
}

// fc4 + tanh update fused: warp per vertex, K=256, 3 outputs
__global__ void fc4_update_kernel(const bf16* __restrict__ h3h, const bf16* __restrict__ h3l,
                                  const float* __restrict__ w, const float* __restrict__ b,
                                  float* __restrict__ x) {
    int gw = (blockIdx.x * blockDim.x + threadIdx.x) >> 5;
    int lane = threadIdx.x & 31;
    if (gw >= NV) return;
    float s0 = 0.f, s1 = 0.f, s2 = 0.f;
    size_t base = (size_t)gw * 256;
#pragma unroll
    for (int k = lane; k < 256; k += 32) {
        float a = __bfloat162float(h3h[base + k]) + __bfloat162float(h3l[base + k]);
        s0 += a * w[k];
        s1 += a * w[256 + k];
        s2 += a * w[512 + k];
    }
#pragma unroll
    for (int off = 16; off > 0; off >>= 1) {
        s0 += __shfl_xor_sync(0xFFFFFFFFu, s0, off);
        s1 += __shfl_xor_sync(0xFFFFFFFFu, s1, off);
        s2 += __shfl_xor_sync(0xFFFFFFFFu, s2, off);
    }
    if (lane == 0) {
        x[3 * gw + 0] += tanhf(s0 + b[0]) * 0.1f;
        x[3 * gw + 1] += tanhf(s1 + b[1]) * 0.1f;
        x[3 * gw + 2] += tanhf(s2 + b[2]) * 0.1f;
    }
}

// ---------------- smoothing ----------------
__global__ void edge_kernel(const float* __restrict__ x, const int* __restrict__ f,
                            float* __restrict__ agg, float* __restrict__ cnt) {
    int i = blockIdx.x * blockDim.x + threadIdx.x;
    if (i >= NFACE) return;
    int i0 = f[3 * i], i1 = f[3 * i + 1], i2 = f[3 * i + 2];
    atomicAdd(&cnt[i0], 1.f);
    atomicAdd(&cnt[i1], 1.f);
    atomicAdd(&cnt[i2], 1.f);
#pragma unroll
    for (int c = 0; c < 3; c++) {
        atomicAdd(&agg[3 * i1 + c], x[3 * i0 + c]);
        atomicAdd(&agg[3 * i2 + c], x[3 * i1 + c]);
        atomicAdd(&agg[3 * i0 + c], x[3 * i2 + c]);
    }
}

__global__ void smooth_final_kernel(const float* __restrict__ agg, const float* __restrict__ cnt,
                                    float* __restrict__ out) {
    int v = blockIdx.x * blockDim.x + threadIdx.x;
    if (v >= NV) return;
    float c = fmaxf(cnt[v], 1.f);
    float inv = 1.f / c;
    out[3 * v + 0] = agg[3 * v + 0] * inv;
    out[3 * v + 1] = agg[3 * v + 1] * inv;
    out[3 * v + 2] = agg[3 * v + 2] * inv;
}

// ---------------- launcher ----------------
static inline int ceil_div(int a, int b) { return (a + b - 1) / b; }

extern "C" void kernel_launch(void* const* d_in, const int* in_sizes, int n_in,
                              void* d_out, int out_size) {
    const float* v      = (const float*)d_in[0];
    const int*   f      = (const int*)d_in[1];
    const float* volume = (const float*)d_in[2];
    const float* fc1_w  = (const float*)d_in[3];
    const float* fc1_b  = (const float*)d_in[4];
    const float* fc2_w  = (const float*)d_in[5];
    const float* fc2_b  = (const float*)d_in[6];
    const float* fc3_w  = (const float*)d_in[7];
    const float* fc3_b  = (const float*)d_in[8];
    const float* fc4_w  = (const float*)d_in[9];
    const float* fc4_b  = (const float*)d_in[10];
    const float* conv_w = (const float*)d_in[11];
    const float* conv_b = (const float*)d_in[12];
    const float* lfc_w  = (const float*)d_in[13];
    const float* lfc_b  = (const float*)d_in[14];
    float* out = (float*)d_out;

    float *px, *pnrm, *pvol1, *pvol2, *pcnt, *pagg, *pconvb;
    bf16 *pcub_h, *pcub_l, *pcat_h, *pcat_l, *ph2_h, *ph2_l, *ph3_h, *ph3_l;
    bf16 *pconvw_h, *pconvw_l, *pfc2w_h, *pfc2w_l, *pfc3w_h, *pfc3w_l;
    cudaGetSymbolAddress((void**)&px, g_x);
    cudaGetSymbolAddress((void**)&pnrm, g_nrm);
    cudaGetSymbolAddress((void**)&pvol1, g_vol1);
    cudaGetSymbolAddress((void**)&pvol2, g_vol2);
    cudaGetSymbolAddress((void**)&pcnt, g_cnt);
    cudaGetSymbolAddress((void**)&pagg, g_agg);
    cudaGetSymbolAddress((void**)&pconvb, g_convb);
    cudaGetSymbolAddress((void**)&pcub_h, g_cubes_h);
    cudaGetSymbolAddress((void**)&pcub_l, g_cubes_l);
    cudaGetSymbolAddress((void**)&pcat_h, g_cat_h);
    cudaGetSymbolAddress((void**)&pcat_l, g_cat_l);
    cudaGetSymbolAddress((void**)&ph2_h, g_h2_h);
    cudaGetSymbolAddress((void**)&ph2_l, g_h2_l);
    cudaGetSymbolAddress((void**)&ph3_h, g_h3_h);
    cudaGetSymbolAddress((void**)&ph3_l, g_h3_l);
    cudaGetSymbolAddress((void**)&pconvw_h, g_convw_h);
    cudaGetSymbolAddress((void**)&pconvw_l, g_convw_l);
    cudaGetSymbolAddress((void**)&pfc2w_h, g_fc2w_h);
    cudaGetSymbolAddress((void**)&pfc2w_l, g_fc2w_l);
    cudaGetSymbolAddress((void**)&pfc3w_h, g_fc3w_h);
    cudaGetSymbolAddress((void**)&pfc3w_l, g_fc3w_l);

    const int SMEM_BYTES = STAGE * 2 * 4;  // 81920
    cudaFuncSetAttribute(gemm_mma_kernel<0>, cudaFuncAttributeMaxDynamicSharedMemorySize, SMEM_BYTES);
    cudaFuncSetAttribute(gemm_mma_kernel<1>, cudaFuncAttributeMaxDynamicSharedMemorySize, SMEM_BYTES);

    const int T = 256;
    const int MT = ceil_div(NV, 128);  // 1172 M-tiles

    // preamble: x = v ; volume pyramid ; fused+split weights ; zero conv-K pad
    copy_kernel<<<ceil_div(NV * 3, T), T>>>(v, px, NV * 3);
    downsample_kernel<<<ceil_div(96 * 96 * 96, T), T>>>(volume, pvol1, 96);
    downsample_kernel<<<ceil_div(48 * 48 * 48, T), T>>>(pvol1, pvol2, 48);
    fuse_conv_lfc_w_kernel<<<ceil_div(3 * 128 * 384, T), T>>>(conv_w, lfc_w, pconvw_h, pconvw_l);
    fuse_conv_lfc_b_kernel<<<ceil_div(3 * 128, T), T>>>(conv_b, lfc_w, lfc_b, pconvb);
    split_weights_kernel<<<ceil_div(3 * 512 * 256, T), T>>>(fc2_w, pfc2w_h, pfc2w_l, 3 * 512 * 256);
    split_weights_kernel<<<ceil_div(3 * 256 * 512, T), T>>>(fc3_w, pfc3w_h, pfc3w_l, 3 * 256 * 512);
    zero_pad_kernel<<<ceil_div(NV * 9, T), T>>>();

    for (int b = 0; b < 3; b++) {
        zero_kernel<<<ceil_div(NV * 3, T), T>>>(pnrm, NV * 3);
        face_normal_kernel<<<ceil_div(NFACE, T), T>>>(px, f, pnrm);
        fc1_kernel<<<ceil_div(NV, 8), 128>>>(px, pnrm, fc1_w + (size_t)b * 128 * 6,
                                             fc1_b + (size_t)b * 128, pcat_h, pcat_l);
        cube_sample_kernel<<<ceil_div(NV * 32, T), T>>>(px, volume, pvol1, pvol2, pcub_h, pcub_l);
        // fused conv+lfc: (N,384) -> cat[:,128:256]
        gemm_mma_kernel<0><<<dim3(MT, 1), 256, SMEM_BYTES>>>(
            pcub_h, pcub_l, 384,
            pconvw_h + (size_t)b * 128 * 384, pconvw_l + (size_t)b * 128 * 384,
            pconvb + (size_t)b * 128, pcat_h + 128, pcat_l + 128, 256, NV, 384);
        // fc2: (N,256) -> (N,512), lrelu
        gemm_mma_kernel<1><<<dim3(MT, 4), 256, SMEM_BYTES>>>(
            pcat_h, pcat_l, 256,
            pfc2w_h + (size_t)b * 512 * 256, pfc2w_l + (size_t)b * 512 * 256,
            fc2_b + (size_t)b * 512, ph2_h, ph2_l, 512, NV, 256);
        // fc3: (N,512) -> (N,256), lrelu
        gemm_mma_kernel<1><<<dim3(MT, 2), 256, SMEM_BYTES>>>(
            ph2_h, ph2_l, 512,
            pfc3w_h + (size_t)b * 256 * 512, pfc3w_l + (size_t)b * 256 * 512,
            fc3_b + (size_t)b * 256, ph3_h, ph3_l, 256, NV, 512);
        // fc4 + tanh update
        fc4_update_kernel<<<ceil_div(NV * 32, T), T>>>(
            ph3_h, ph3_l, fc4_w + (size_t)b * 3 * 256, fc4_b + (size_t)b * 3, px);
    }

    // one Laplacian smoothing pass (n_smooth fixed at 1 by setup_inputs)
    zero_kernel<<<ceil_div(NV, T), T>>>(pcnt, NV);
    zero_kernel<<<ceil_div(NV * 3, T), T>>>(pagg, NV * 3);
    edge_kernel<<<ceil_div(NFACE, T), T>>>(px, f, pagg, pcnt);
    smooth_final_kernel<<<ceil_div(NV, T), T>>>(pagg, pcnt, out);
}

// round 4
// speedup vs baseline: 3.9934x; 1.0284x over previous
#include <cuda_runtime.h>
#include <cuda_bf16.h>
#include <math.h>

#define NV    150000
#define NFACE 300000
typedef __nv_bfloat16 bf16;

// ---------------- scratch (device globals; no allocs allowed) ----------------
__device__ float g_x[NV * 3];
__device__ float g_nrm[NV * 3];
__device__ bf16  g_cubes_h[(size_t)NV * 384];
__device__ bf16  g_cubes_l[(size_t)NV * 384];
__device__ bf16  g_cat_h[(size_t)NV * 256];    // [:,0:128]=h1, [:,128:256]=conv+lfc out
__device__ bf16  g_cat_l[(size_t)NV * 256];
__device__ bf16  g_h2_h[(size_t)NV * 512];
__device__ bf16  g_h2_l[(size_t)NV * 512];
__device__ bf16  g_h3_h[(size_t)NV * 256];
__device__ bf16  g_h3_l[(size_t)NV * 256];
__device__ float g_vol1[96 * 96 * 96];
__device__ float g_vol2[48 * 48 * 48];
__device__ float g_cnt[NV];
__device__ float g_agg[NV * 3];
// pre-split weights (conv fused with lfc: W' = lfc_w @ conv_w, padded K 375->384)
__device__ bf16  g_convw_h[3 * 128 * 384];
__device__ bf16  g_convw_l[3 * 128 * 384];
__device__ float g_convb[3 * 128];
__device__ bf16  g_fc2w_h[3 * 512 * 256];
__device__ bf16  g_fc2w_l[3 * 512 * 256];
__device__ bf16  g_fc3w_h[3 * 256 * 512];
__device__ bf16  g_fc3w_l[3 * 256 * 512];

__device__ __forceinline__ void split_store(bf16* __restrict__ H, bf16* __restrict__ L,
                                            size_t idx, float v) {
    bf16 h = __float2bfloat16(v);
    H[idx] = h;
    L[idx] = __float2bfloat16(v - __bfloat162float(h));
}

// ---------------- utility kernels ----------------
__global__ void zero_kernel(float* p, int n) {
    int i = blockIdx.x * blockDim.x + threadIdx.x;
    if (i < n) p[i] = 0.f;
}
__global__ void copy_kernel(const float* __restrict__ a, float* __restrict__ b, int n) {
    int i = blockIdx.x * blockDim.x + threadIdx.x;
    if (i < n) b[i] = a[i];
}
__global__ void zero_pad_kernel() {
    int i = blockIdx.x * blockDim.x + threadIdx.x;
    if (i >= NV * 9) return;
    int v = i / 9, p = i - 9 * v;
    size_t idx = (size_t)v * 384 + 375 + p;
    g_cubes_h[idx] = __float2bfloat16(0.f);
    g_cubes_l[idx] = __float2bfloat16(0.f);
}
__global__ void split_weights_kernel(const float* __restrict__ src, bf16* __restrict__ h,
                                     bf16* __restrict__ l, int n) {
    int i = blockIdx.x * blockDim.x + threadIdx.x;
    if (i < n) split_store(h, l, i, src[i]);
}
// W' = lfc_w @ conv_w  (per block), fp32 accum, split-stored, K padded to 384
__global__ void fuse_conv_lfc_w_kernel(const float* __restrict__ conv_w,
                                       const float* __restrict__ lfc_w,
                                       bf16* __restrict__ wh, bf16* __restrict__ wl) {
    int i = blockIdx.x * blockDim.x + threadIdx.x;
    if (i >= 3 * 128 * 384) return;
    int k = i % 384;
    int o = (i / 384) % 128;
    int b = i / (384 * 128);
    float s = 0.f;
    if (k < 375) {
        const float* lw = lfc_w + (size_t)b * 128 * 128 + (size_t)o * 128;
        const float* cw = conv_w + (size_t)b * 128 * 375 + k;
#pragma unroll 4
        for (int j = 0; j < 128; j++) s += lw[j] * cw[(size_t)j * 375];
    }
    split_store(wh, wl, i, s);
}
// b' = lfc_w @ conv_b + lfc_b
__global__ void fuse_conv_lfc_b_kernel(const float* __restrict__ conv_b,
                                       const float* __restrict__ lfc_w,
                                       const float* __restrict__ lfc_b,
                                       float* __restrict__ bout) {
    int i = blockIdx.x * blockDim.x + threadIdx.x;
    if (i >= 3 * 128) return;
    int o = i % 128, b = i / 128;
    float s = lfc_b[(size_t)b * 128 + o];
    const float* lw = lfc_w + (size_t)b * 128 * 128 + (size_t)o * 128;
    const float* cb = conv_b + (size_t)b * 128;
    for (int j = 0; j < 128; j++) s += lw[j] * cb[j];
    bout[i] = s;
}

// mean-pool 2x2x2
__global__ void downsample_kernel(const float* __restrict__ src, float* __restrict__ dst, int Ld) {
    int i = blockIdx.x * blockDim.x + threadIdx.x;
    int tot = Ld * Ld * Ld;
    if (i >= tot) return;
    int z = i % Ld;
    int y = (i / Ld) % Ld;
    int x = i / (Ld * Ld);
    int Ls = Ld * 2;
    const float* s = src + ((size_t)(2 * x) * Ls + (size_t)(2 * y)) * Ls + (size_t)(2 * z);
    float sum = 0.f;
#pragma unroll
    for (int a = 0; a < 2; a++)
#pragma unroll
        for (int b = 0; b < 2; b++)
#pragma unroll
            for (int c = 0; c < 2; c++)
                sum += s[((size_t)a * Ls + b) * Ls + c];
    dst[i] = sum * 0.125f;
}

// ---------------- vertex normals (face scatter) ----------------
__global__ void face_normal_kernel(const float* __restrict__ x, const int* __restrict__ f,
                                   float* __restrict__ nrm) {
    int i = blockIdx.x * blockDim.x + threadIdx.x;
    if (i >= NFACE) return;
    int i0 = f[3 * i], i1 = f[3 * i + 1], i2 = f[3 * i + 2];
    float v0x = x[3 * i0], v0y = x[3 * i0 + 1], v0z = x[3 * i0 + 2];
    float v1x = x[3 * i1], v1y = x[3 * i1 + 1], v1z = x[3 * i1 + 2];
    float v2x = x[3 * i2], v2y = x[3 * i2 + 1], v2z = x[3 * i2 + 2];
    float e1x = v1x - v0x, e1y = v1y - v0y, e1z = v1z - v0z;
    float e2x = v2x - v0x, e2y = v2y - v0y, e2z = v2z - v0z;
    float nx = e1y * e2z - e1z * e2y;
    float ny = e1z * e2x - e1x * e2z;
    float nz = e1x * e2y - e1y * e2x;
    atomicAdd(&nrm[3 * i0 + 0], nx); atomicAdd(&nrm[3 * i0 + 1], ny); atomicAdd(&nrm[3 * i0 + 2], nz);
    atomicAdd(&nrm[3 * i1 + 0], nx); atomicAdd(&nrm[3 * i1 + 1], ny); atomicAdd(&nrm[3 * i1 + 2], nz);
    atomicAdd(&nrm[3 * i2 + 0], nx); atomicAdd(&nrm[3 * i2 + 1], ny); atomicAdd(&nrm[3 * i2 + 2], nz);
}

// fc1: [x, n/|n|] (6) -> 128, lrelu, split-write into cat[:, 0:128]
__global__ void fc1_kernel(const float* __restrict__ x, const float* __restrict__ nrm,
                           const float* __restrict__ w, const float* __restrict__ b,
                           bf16* __restrict__ cat_h, bf16* __restrict__ cat_l) {
    __shared__ float sw[128 * 6];
    __shared__ float sb[128];
    __shared__ float sin_[8][6];
    int o = threadIdx.x;
#pragma unroll
    for (int j = o; j < 768; j += 128) sw[j] = w[j];
    sb[o] = b[o];
    int v0 = blockIdx.x * 8;
    if (o < 8) {
        int v = v0 + o;
        if (v < NV) {
            float nx = nrm[3 * v], ny = nrm[3 * v + 1], nz = nrm[3 * v + 2];
            float len = sqrtf(nx * nx + ny * ny + nz * nz);
            float inv = 1.f / fmaxf(len, 1e-12f);
            sin_[o][0] = x[3 * v]; sin_[o][1] = x[3 * v + 1]; sin_[o][2] = x[3 * v + 2];
            sin_[o][3] = nx * inv; sin_[o][4] = ny * inv; sin_[o][5] = nz * inv;
        }
    }
    __syncthreads();
#pragma unroll
    for (int t = 0; t < 8; t++) {
        int v = v0 + t;
        if (v >= NV) break;
        float acc = sb[o];
#pragma unroll
        for (int k = 0; k < 6; k++) acc += sin_[t][k] * sw[o * 6 + k];
        acc = acc > 0.f ? acc : 0.15f * acc;
        split_store(cat_h, cat_l, (size_t)v * 256 + o, acc);
    }
}

// ---------------- multiscale cube sampling, split-bf16 output (lda=384) ----------------
__global__ void cube_sample_kernel(const float* __restrict__ x, const float* __restrict__ vol0,
                                   const float* __restrict__ vol1, const float* __restrict__ vol2,
                                   bf16* __restrict__ ch, bf16* __restrict__ cl) {
    int gw = (blockIdx.x * blockDim.x + threadIdx.x) >> 5;
    int lane = threadIdx.x & 31;
    if (gw >= NV) return;
    float px = x[3 * gw], py = x[3 * gw + 1], pz = x[3 * gw + 2];
#pragma unroll
    for (int n = 0; n < 3; n++) {
        const float* vol = (n == 0) ? vol0 : ((n == 1) ? vol1 : vol2);
        int Ln = 192 >> n;
        float mul = (float)(96 >> n);
        int ix = (int)rintf((px + 1.f) * mul);
        int iy = (int)rintf((py + 1.f) * mul);
        int iz = (int)rintf((pz + 1.f) * mul);
        int hi = Ln - 3;
        ix = min(max(ix, 2), hi);
        iy = min(max(iy, 2), hi);
        iz = min(max(iz, 2), hi);
        for (int j = lane; j < 125; j += 32) {
            int a = j / 25, r = j - 25 * a;
            int bb = r / 5, c = r - 5 * bb;
            int X = ix + a - 2, Y = iy + bb - 2, Z = iz + c - 2;
            float val = vol[((size_t)X * Ln + Y) * Ln + Z];
            split_store(ch, cl, (size_t)gw * 384 + n * 125 + j, val);
        }
    }
}

// ---------------- pipelined split-bf16 MMA GEMM (ldmatrix fragment loads) ----------------
// C[M,Nout] = A[M,K] @ W[Nout,K]^T + bias; A/W as (hi,lo) bf16 planes.
// BM=128, BN=128, BK=32, 256 threads (8 warps: 2m x 4n, warp tile 64x32).
// 2-stage cp.async pipeline, 80KB dynamic smem. Fragments via LDSM.x4.
#define SAS   20                    // smem row stride in u32 (64B data + 16B pad)
#define PLANE (128 * SAS)           // u32 per plane
#define STAGE (4 * PLANE)           // u32 per stage (Ah, Al, Wh, Wl)

__device__ __forceinline__ void mma16816(float* d, const unsigned* a, const unsigned* b) {
    asm volatile(
        "mma.sync.aligned.m16n8k16.row.col.f32.bf16.bf16.f32 "
        "{%0,%1,%2,%3}, {%4,%5,%6,%7}, {%8,%9}, {%0,%1,%2,%3};\n"
        : "+f"(d[0]), "+f"(d[1]), "+f"(d[2]), "+f"(d[3])
        : "r"(a[0]), "r"(a[1]), "r"(a[2]), "r"(a[3]), "r"(b[0]), "r"(b[1]));
}
__device__ __forceinline__ void ldsm4(unsigned addr, unsigned* r) {
    asm volatile("ldmatrix.sync.aligned.m8n8.x4.shared.b16 {%0,%1,%2,%3}, [%4];\n"
                 : "=r"(r[0]), "=r"(r[1]), "=r"(r[2]), "=r"(r[3]) : "r"(addr));
}
__device__ __forceinline__ void cp16(unsigned dst, const void* src, int sz) {
    asm volatile("cp.async.cg.shared.global [%0], [%1], 16, %2;\n"
                 :: "r"(dst), "l"(src), "r"(sz));
}
__device__ __forceinline__ void cp_commit() { asm volatile("cp.async.commit_group;\n"); }
template <int N>
__device__ __forceinline__ void cp_wait() { asm volatile("cp.async.wait_group %0;\n" :: "n"(N)); }

extern __shared__ unsigned dynsmem[];

__device__ __forceinline__ void load_tiles(unsigned sbase,
                                           const bf16* __restrict__ Ah, const bf16* __restrict__ Al,
                                           const bf16* __restrict__ Wh, const bf16* __restrict__ Wl,
                                           int m0, int n0, int k0, int lda, int K, int M, int tid) {
#pragma unroll
    for (int l = 0; l < 2; l++) {
        int idx = tid + l * 256;
        int row = idx >> 2, q = idx & 3;
        int gr = m0 + row;
        int sz = gr < M ? 16 : 0;
        int grc = gr < M ? gr : (M - 1);
        size_t offA = (size_t)grc * lda + k0 + q * 8;
        unsigned d = sbase + (unsigned)(row * SAS + q * 4) * 4u;
        cp16(d, Ah + offA, sz);
        cp16(d + PLANE * 4u, Al + offA, sz);
        size_t offW = (size_t)(n0 + row) * K + k0 + q * 8;
        cp16(d + 2u * PLANE * 4u, Wh + offW, 16);
        cp16(d + 3u * PLANE * 4u, Wl + offW, 16);
    }
    cp_commit();
}

template <int ACT>  // 0 none, 1 lrelu(0.15)
__global__ __launch_bounds__(256, 2) void gemm_mma_kernel(
    const bf16* __restrict__ Ah, const bf16* __restrict__ Al, int lda,
    const bf16* __restrict__ Wh, const bf16* __restrict__ Wl,
    const float* __restrict__ bias,
    bf16* __restrict__ Ch, bf16* __restrict__ Cl, int ldc,
    int M, int K) {
    int tid = threadIdx.x;
    int wid = tid >> 5, lane = tid & 31;
    int wm = wid & 1, wn = wid >> 1;       // 2 m-warps x 4 n-warps
    int g = lane >> 2, tg = lane & 3;
    int m0 = blockIdx.x * 128;
    int n0 = blockIdx.y * 128;

    unsigned smem_addr = (unsigned)__cvta_generic_to_shared(dynsmem);

    // ldmatrix per-lane address offsets (bytes, within a plane)
    // A x4: m0=rows0-7/k0-7, m1=rows8-15/k0-7, m2=rows0-7/k8-15, m3=rows8-15/k8-15
    unsigned aOff[4];
#pragma unroll
    for (int fm = 0; fm < 4; fm++) {
        int row = wm * 64 + fm * 16 + (lane & 15);
        aOff[fm] = (unsigned)(row * SAS) * 4u + ((lane >> 4) & 1) * 16u;
    }
    // B x4 (two 8-col n-chunks): m0=n0-7/k0-7, m1=n0-7/k8-15, m2=n8-15/k0-7, m3=n8-15/k8-15
    unsigned bOff[2];
#pragma unroll
    for (int cp = 0; cp < 2; cp++) {
        int row = wn * 32 + cp * 16 + (lane & 7) + ((lane >> 4) & 1) * 8;
        bOff[cp] = (unsigned)(row * SAS) * 4u + ((lane >> 3) & 1) * 16u;
    }

    float acc[4][4][4];
#pragma unroll
    for (int i = 0; i < 4; i++)
#pragma unroll
        for (int j = 0; j < 4; j++)
#pragma unroll
            for (int k = 0; k < 4; k++) acc[i][j][k] = 0.f;

    int nIter = K >> 5;
    load_tiles(smem_addr, Ah, Al, Wh, Wl, m0, n0, 0, lda, K, M, tid);

    for (int it = 0; it < nIter; it++) {
        if (it + 1 < nIter) {
            load_tiles(smem_addr + ((it + 1) & 1) * (STAGE * 4u),
                       Ah, Al, Wh, Wl, m0, n0, (it + 1) << 5, lda, K, M, tid);
            cp_wait<1>();
        } else {
            cp_wait<0>();
        }
        __syncthreads();

        unsigned sb = smem_addr + (it & 1) * (STAGE * 4u);
        unsigned sAh = sb;
        unsigned sAl = sb + PLANE * 4u;
        unsigned sWh = sb + 2u * PLANE * 4u;
        unsigned sWl = sb + 3u * PLANE * 4u;

#pragma unroll
        for (int ks = 0; ks < 2; ks++) {
            unsigned kb = (unsigned)ks * 32u;
            unsigned ah[4][4], al[4][4];
#pragma unroll
            for (int fm = 0; fm < 4; fm++) {
                ldsm4(sAh + aOff[fm] + kb, ah[fm]);
                ldsm4(sAl + aOff[fm] + kb, al[fm]);
            }
            unsigned bh[4][2], bl[4][2];
#pragma unroll
            for (int cp = 0; cp < 2; cp++) {
                unsigned t[4];
                ldsm4(sWh + bOff[cp] + kb, t);
                bh[2 * cp][0] = t[0]; bh[2 * cp][1] = t[1];
                bh[2 * cp + 1][0] = t[2]; bh[2 * cp + 1][1] = t[3];
                ldsm4(sWl + bOff[cp] + kb, t);
                bl[2 * cp][0] = t[0]; bl[2 * cp][1] = t[1];
                bl[2 * cp + 1][0] = t[2]; bl[2 * cp + 1][1] = t[3];
            }
#pragma unroll
            for (int ch = 0; ch < 4; ch++) {
#pragma unroll
                for (int fm = 0; fm < 4; fm++) {
                    mma16816(acc[fm][ch], ah[fm], bh[ch]);
                    mma16816(acc[fm][ch], ah[fm], bl[ch]);
                    mma16816(acc[fm][ch], al[fm], bh[ch]);
                }
            }
        }
        __syncthreads();
    }

    // epilogue: packed bf16x2 stores
#pragma unroll
    for (int fm = 0; fm < 4; fm++) {
        int r0 = m0 + wm * 64 + fm * 16 + g;
#pragma unroll
        for (int ch = 0; ch < 4; ch++) {
            int c0 = n0 + wn * 32 + ch * 8 + 2 * tg;
            float b0 = bias[c0], b1 = bias[c0 + 1];
#pragma unroll
            for (int half = 0; half < 2; half++) {
                int gr = r0 + half * 8;
                if (gr >= M) continue;
                float v0 = acc[fm][ch][half * 2 + 0] + b0;
                float v1 = acc[fm][ch][half * 2 + 1] + b1;
                if (ACT == 1) {
                    v0 = v0 > 0.f ? v0 : 0.15f * v0;
                    v1 = v1 > 0.f ? v1 : 0.15f * v1;
                }
                bf16 h0 = __float2bfloat16(v0);
                bf16 h1 = __float2bfloat16(v1);
                bf16 l0 = __float2bfloat16(v0 - __bfloat162float(h0));
                bf16 l1 = __float2bfloat16(v1 - __bfloat162float(h1));
                size_t off = (size_t)gr * ldc + c0;
                *(__nv_bfloat162*)(Ch + off) = __nv_bfloat162(h0, h1);
                *(__nv_bfloat162*)(Cl + off) = __nv_bfloat162(l0, l1);
            }
        }
    }
}

// fc4 + tanh update fused: warp per vertex, K=256, 3 outputs
__global__ void fc4_update_kernel(const bf16* __restrict__ h3h, const bf16* __restrict__ h3l,
                                  const float* __restrict__ w, const float* __restrict__ b,
                                  float* __restrict__ x) {
    int gw = (blockIdx.x * blockDim.x + threadIdx.x) >> 5;
    int lane = threadIdx.x & 31;
    if (gw >= NV) return;
    float s0 = 0.f, s1 = 0.f, s2 = 0.f;
    size_t base = (size_t)gw * 256;
#pragma unroll
    for (int k = lane; k < 256; k += 32) {
        float a = __bfloat162float(h3h[base + k]) + __bfloat162float(h3l[base + k]);
        s0 += a * w[k];
        s1 += a * w[256 + k];
        s2 += a * w[512 + k];
    }
#pragma unroll
    for (int off = 16; off > 0; off >>= 1) {
        s0 += __shfl_xor_sync(0xFFFFFFFFu, s0, off);
        s1 += __shfl_xor_sync(0xFFFFFFFFu, s1, off);
        s2 += __shfl_xor_sync(0xFFFFFFFFu, s2, off);
    }
    if (lane == 0) {
        x[3 * gw + 0] += tanhf(s0 + b[0]) * 0.1f;
        x[3 * gw + 1] += tanhf(s1 + b[1]) * 0.1f;
        x[3 * gw + 2] += tanhf(s2 + b[2]) * 0.1f;
    }
}

// ---------------- smoothing ----------------
__global__ void edge_kernel(const float* __restrict__ x, const int* __restrict__ f,
                            float* __restrict__ agg, float* __restrict__ cnt) {
    int i = blockIdx.x * blockDim.x + threadIdx.x;
    if (i >= NFACE) return;
    int i0 = f[3 * i], i1 = f[3 * i + 1], i2 = f[3 * i + 2];
    atomicAdd(&cnt[i0], 1.f);
    atomicAdd(&cnt[i1], 1.f);
    atomicAdd(&cnt[i2], 1.f);
#pragma unroll
    for (int c = 0; c < 3; c++) {
        atomicAdd(&agg[3 * i1 + c], x[3 * i0 + c]);
        atomicAdd(&agg[3 * i2 + c], x[3 * i1 + c]);
        atomicAdd(&agg[3 * i0 + c], x[3 * i2 + c]);
    }
}

__global__ void smooth_final_kernel(const float* __restrict__ agg, const float* __restrict__ cnt,
                                    float* __restrict__ out) {
    int v = blockIdx.x * blockDim.x + threadIdx.x;
    if (v >= NV) return;
    float c = fmaxf(cnt[v], 1.f);
    float inv = 1.f / c;
    out[3 * v + 0] = agg[3 * v + 0] * inv;
    out[3 * v + 1] = agg[3 * v + 1] * inv;
    out[3 * v + 2] = agg[3 * v + 2] * inv;
}

// ---------------- launcher ----------------
static inline int ceil_div(int a, int b) { return (a + b - 1) / b; }

extern "C" void kernel_launch(void* const* d_in, const int* in_sizes, int n_in,
                              void* d_out, int out_size) {
    const float* v      = (const float*)d_in[0];
    const int*   f      = (const int*)d_in[1];
    const float* volume = (const float*)d_in[2];
    const float* fc1_w  = (const float*)d_in[3];
    const float* fc1_b  = (const float*)d_in[4];
    const float* fc2_w  = (const float*)d_in[5];
    const float* fc2_b  = (const float*)d_in[6];
    const float* fc3_w  = (const float*)d_in[7];
    const float* fc3_b  = (const float*)d_in[8];
    const float* fc4_w  = (const float*)d_in[9];
    const float* fc4_b  = (const float*)d_in[10];
    const float* conv_w = (const float*)d_in[11];
    const float* conv_b = (const float*)d_in[12];
    const float* lfc_w  = (const float*)d_in[13];
    const float* lfc_b  = (const float*)d_in[14];
    float* out = (float*)d_out;

    float *px, *pnrm, *pvol1, *pvol2, *pcnt, *pagg, *pconvb;
    bf16 *pcub_h, *pcub_l, *pcat_h, *pcat_l, *ph2_h, *ph2_l, *ph3_h, *ph3_l;
    bf16 *pconvw_h, *pconvw_l, *pfc2w_h, *pfc2w_l, *pfc3w_h, *pfc3w_l;
    cudaGetSymbolAddress((void**)&px, g_x);
    cudaGetSymbolAddress((void**)&pnrm, g_nrm);
    cudaGetSymbolAddress((void**)&pvol1, g_vol1);
    cudaGetSymbolAddress((void**)&pvol2, g_vol2);
    cudaGetSymbolAddress((void**)&pcnt, g_cnt);
    cudaGetSymbolAddress((void**)&pagg, g_agg);
    cudaGetSymbolAddress((void**)&pconvb, g_convb);
    cudaGetSymbolAddress((void**)&pcub_h, g_cubes_h);
    cudaGetSymbolAddress((void**)&pcub_l, g_cubes_l);
    cudaGetSymbolAddress((void**)&pcat_h, g_cat_h);
    cudaGetSymbolAddress((void**)&pcat_l, g_cat_l);
    cudaGetSymbolAddress((void**)&ph2_h, g_h2_h);
    cudaGetSymbolAddress((void**)&ph2_l, g_h2_l);
    cudaGetSymbolAddress((void**)&ph3_h, g_h3_h);
    cudaGetSymbolAddress((void**)&ph3_l, g_h3_l);
    cudaGetSymbolAddress((void**)&pconvw_h, g_convw_h);
    cudaGetSymbolAddress((void**)&pconvw_l, g_convw_l);
    cudaGetSymbolAddress((void**)&pfc2w_h, g_fc2w_h);
    cudaGetSymbolAddress((void**)&pfc2w_l, g_fc2w_l);
    cudaGetSymbolAddress((void**)&pfc3w_h, g_fc3w_h);
    cudaGetSymbolAddress((void**)&pfc3w_l, g_fc3w_l);

    const int SMEM_BYTES = STAGE * 2 * 4;  // 81920
    cudaFuncSetAttribute(gemm_mma_kernel<0>, cudaFuncAttributeMaxDynamicSharedMemorySize, SMEM_BYTES);
    cudaFuncSetAttribute(gemm_mma_kernel<1>, cudaFuncAttributeMaxDynamicSharedMemorySize, SMEM_BYTES);

    const int T = 256;
    const int MT = ceil_div(NV, 128);  // 1172 M-tiles

    // preamble
    copy_kernel<<<ceil_div(NV * 3, T), T>>>(v, px, NV * 3);
    downsample_kernel<<<ceil_div(96 * 96 * 96, T), T>>>(volume, pvol1, 96);
    downsample_kernel<<<ceil_div(48 * 48 * 48, T), T>>>(pvol1, pvol2, 48);
    fuse_conv_lfc_w_kernel<<<ceil_div(3 * 128 * 384, T), T>>>(conv_w, lfc_w, pconvw_h, pconvw_l);
    fuse_conv_lfc_b_kernel<<<ceil_div(3 * 128, T), T>>>(conv_b, lfc_w, lfc_b, pconvb);
    split_weights_kernel<<<ceil_div(3 * 512 * 256, T), T>>>(fc2_w, pfc2w_h, pfc2w_l, 3 * 512 * 256);
    split_weights_kernel<<<ceil_div(3 * 256 * 512, T), T>>>(fc3_w, pfc3w_h, pfc3w_l, 3 * 256 * 512);
    zero_pad_kernel<<<ceil_div(NV * 9, T), T>>>();

    for (int b = 0; b < 3; b++) {
        zero_kernel<<<ceil_div(NV * 3, T), T>>>(pnrm, NV * 3);
        face_normal_kernel<<<ceil_div(NFACE, T), T>>>(px, f, pnrm);
        fc1_kernel<<<ceil_div(NV, 8), 128>>>(px, pnrm, fc1_w + (size_t)b * 128 * 6,
                                             fc1_b + (size_t)b * 128, pcat_h, pcat_l);
        cube_sample_kernel<<<ceil_div(NV * 32, T), T>>>(px, volume, pvol1, pvol2, pcub_h, pcub_l);
        // fused conv+lfc: (N,384) -> cat[:,128:256]
        gemm_mma_kernel<0><<<dim3(MT, 1), 256, SMEM_BYTES>>>(
            pcub_h, pcub_l, 384,
            pconvw_h + (size_t)b * 128 * 384, pconvw_l + (size_t)b * 128 * 384,
            pconvb + (size_t)b * 128, pcat_h + 128, pcat_l + 128, 256, NV, 384);
        // fc2: (N,256) -> (N,512), lrelu
        gemm_mma_kernel<1><<<dim3(MT, 4), 256, SMEM_BYTES>>>(
            pcat_h, pcat_l, 256,
            pfc2w_h + (size_t)b * 512 * 256, pfc2w_l + (size_t)b * 512 * 256,
            fc2_b + (size_t)b * 512, ph2_h, ph2_l, 512, NV, 256);
        // fc3: (N,512) -> (N,256), lrelu
        gemm_mma_kernel<1><<<dim3(MT, 2), 256, SMEM_BYTES>>>(
            ph2_h, ph2_l, 512,
            pfc3w_h + (size_t)b * 256 * 512, pfc3w_l + (size_t)b * 256 * 512,
            fc3_b + (size_t)b * 256, ph3_h, ph3_l, 256, NV, 512);
        // fc4 + tanh update
        fc4_update_kernel<<<ceil_div(NV * 32, T), T>>>(
            ph3_h, ph3_l, fc4_w + (size_t)b * 3 * 256, fc4_b + (size_t)b * 3, px);
    }

    // one Laplacian smoothing pass (n_smooth fixed at 1 by setup_inputs)
    zero_kernel<<<ceil_div(NV, T), T>>>(pcnt, NV);
    zero_kernel<<<ceil_div(NV * 3, T), T>>>(pagg, NV * 3);
    edge_kernel<<<ceil_div(NFACE, T), T>>>(px, f, pagg, pcnt);
    smooth_final_kernel<<<ceil_div(NV, T), T>>>(pagg, pcnt, out);
}